// round 1
// baseline (speedup 1.0000x reference)
#include <cuda_runtime.h>
#include <cuda_bf16.h>

#define N_CP   128
#define N_DATA 32768
#define BATCH  16
#define TPB    128

// inputs (metadata order): [0] input [16,3] (UNUSED by reference),
// [1] control_points [16,3,128], [2] weights [16,1,128], [3] N [128,32768]
// output: dp [16,3,32768] float32

__global__ __launch_bounds__(TPB) void nurbs_sparse_kernel(
    const float* __restrict__ cp,    // [16,3,128]
    const float* __restrict__ w,     // [16,1,128]
    const float* __restrict__ Nmat,  // [128, 32768]
    float* __restrict__ out)         // [16,3,32768]
{
    // s_pack[c][b] = (w[b,c], cp[b,0,c]*w, cp[b,1,c]*w, cp[b,2,c]*w)
    __shared__ float4 s_pack[N_CP * BATCH];   // 32 KB

    const int tid = threadIdx.x;

    // Cooperative prologue: 2048 (c,b) pairs, 16 per thread.
    for (int idx = tid; idx < N_CP * BATCH; idx += TPB) {
        const int c = idx >> 4;     // idx / BATCH
        const int b = idx & 15;     // idx % BATCH
        const float wv = w[b * N_CP + c];
        float4 p;
        p.x = wv;
        p.y = cp[(b * 3 + 0) * N_CP + c] * wv;
        p.z = cp[(b * 3 + 1) * N_CP + c] * wv;
        p.w = cp[(b * 3 + 2) * N_CP + c] * wv;
        s_pack[c * BATCH + b] = p;
    }
    __syncthreads();

    const int n = blockIdx.x * TPB + tid;

    // 64 accumulators: [b][0]=W, [b][1..3]=numerator dims
    float acc[BATCH][4];
    #pragma unroll
    for (int b = 0; b < BATCH; b++) {
        #pragma unroll
        for (int j = 0; j < 4; j++) acc[b][j] = 0.0f;
    }

    // Scan all 128 rows of N for this column; only ~4 are nonzero
    // (degree-3 basis), and the band is warp-coherent, so the branch
    // skips 124/128 bodies. Exact regardless of sparsity pattern.
    #pragma unroll 4
    for (int c = 0; c < N_CP; c++) {
        const float nv = Nmat[c * N_DATA + n];
        if (nv != 0.0f) {
            #pragma unroll
            for (int b = 0; b < BATCH; b++) {
                const float4 p = s_pack[c * BATCH + b];  // warp-uniform broadcast
                acc[b][0] = fmaf(p.x, nv, acc[b][0]);
                acc[b][1] = fmaf(p.y, nv, acc[b][1]);
                acc[b][2] = fmaf(p.z, nv, acc[b][2]);
                acc[b][3] = fmaf(p.w, nv, acc[b][3]);
            }
        }
    }

    // Epilogue: divide by W and store (coalesced across n).
    #pragma unroll
    for (int b = 0; b < BATCH; b++) {
        const float inv = 1.0f / acc[b][0];   // W >= 0.1 (partition of unity, w>=0.1)
        #pragma unroll
        for (int d = 0; d < 3; d++)
            out[(b * 3 + d) * N_DATA + n] = acc[b][d + 1] * inv;
    }
}

extern "C" void kernel_launch(void* const* d_in, const int* in_sizes, int n_in,
                              void* d_out, int out_size) {
    const float* cp   = (const float*)d_in[1];
    const float* w    = (const float*)d_in[2];
    const float* Nmat = (const float*)d_in[3];
    float* out = (float*)d_out;

    nurbs_sparse_kernel<<<N_DATA / TPB, TPB>>>(cp, w, Nmat, out);
}

// round 2
// speedup vs baseline: 1.3414x; 1.3414x over previous
#include <cuda_runtime.h>
#include <cuda_bf16.h>

#define N_CP   128
#define N_DATA 32768
#define BATCH  16
#define TPB    128
#define CHUNK  32   // independent loads per phase -> MLP 32 per warp

// inputs (metadata order): [0] input [16,3] (UNUSED by reference),
// [1] control_points [16,3,128], [2] weights [16,1,128], [3] N [128,32768]
// output: dp [16,3,32768] float32

__global__ __launch_bounds__(TPB) void nurbs_sparse_kernel(
    const float* __restrict__ cp,    // [16,3,128]
    const float* __restrict__ w,     // [16,1,128]
    const float* __restrict__ Nmat,  // [128, 32768]
    float* __restrict__ out)         // [16,3,32768]
{
    // s_pack[c][b] = (w[b,c], cp[b,0,c]*w, cp[b,1,c]*w, cp[b,2,c]*w)
    __shared__ float4 s_pack[N_CP * BATCH];   // 32 KB

    const int tid = threadIdx.x;

    // Cooperative prologue: 2048 (c,b) pairs, 16 per thread.
    for (int idx = tid; idx < N_CP * BATCH; idx += TPB) {
        const int c = idx >> 4;
        const int b = idx & 15;
        const float wv = w[b * N_CP + c];
        float4 p;
        p.x = wv;
        p.y = cp[(b * 3 + 0) * N_CP + c] * wv;
        p.z = cp[(b * 3 + 1) * N_CP + c] * wv;
        p.w = cp[(b * 3 + 2) * N_CP + c] * wv;
        s_pack[c * BATCH + b] = p;
    }
    __syncthreads();

    const int n = blockIdx.x * TPB + tid;

    // 64 accumulators: [b][0]=W, [b][1..3]=numerator dims
    float acc[BATCH][4];
    #pragma unroll
    for (int b = 0; b < BATCH; b++) {
        #pragma unroll
        for (int j = 0; j < 4; j++) acc[b][j] = 0.0f;
    }

    const float* __restrict__ colp = Nmat + n;

    // Phase-decoupled scan: 32 independent LDGs issued back-to-back
    // (MLP=32 per warp), THEN the branchy sparse-FMA pass. Only ~4 of
    // 128 rows are nonzero (degree-3 basis) and the band is
    // warp-coherent, so 124/128 bodies are skipped. Exact regardless
    // of sparsity pattern.
    for (int ch = 0; ch < N_CP / CHUNK; ch++) {
        float nv[CHUNK];
        #pragma unroll
        for (int k = 0; k < CHUNK; k++)
            nv[k] = colp[(ch * CHUNK + k) * N_DATA];

        #pragma unroll
        for (int k = 0; k < CHUNK; k++) {
            if (nv[k] != 0.0f) {
                const int c = ch * CHUNK + k;
                #pragma unroll
                for (int b = 0; b < BATCH; b++) {
                    const float4 p = s_pack[c * BATCH + b];  // uniform broadcast
                    acc[b][0] = fmaf(p.x, nv[k], acc[b][0]);
                    acc[b][1] = fmaf(p.y, nv[k], acc[b][1]);
                    acc[b][2] = fmaf(p.z, nv[k], acc[b][2]);
                    acc[b][3] = fmaf(p.w, nv[k], acc[b][3]);
                }
            }
        }
    }

    // Epilogue: divide by W and store (coalesced across n).
    #pragma unroll
    for (int b = 0; b < BATCH; b++) {
        const float inv = 1.0f / acc[b][0];
        #pragma unroll
        for (int d = 0; d < 3; d++)
            out[(b * 3 + d) * N_DATA + n] = acc[b][d + 1] * inv;
    }
}

extern "C" void kernel_launch(void* const* d_in, const int* in_sizes, int n_in,
                              void* d_out, int out_size) {
    const float* cp   = (const float*)d_in[1];
    const float* w    = (const float*)d_in[2];
    const float* Nmat = (const float*)d_in[3];
    float* out = (float*)d_out;

    nurbs_sparse_kernel<<<N_DATA / TPB, TPB>>>(cp, w, Nmat, out);
}